// round 14
// baseline (speedup 1.0000x reference)
#include <cuda_runtime.h>
#include <cuda_fp16.h>
#include <cstdint>

// Problem constants (fixed by dataset):
// b=2, s=256, C=128, H=W=16, YH=XH=CH=2 -> nH=8 heads, c=64, h=w=8, D=4096
// mask: 16x16 token grid, radius-1 neighborhood (<=9 keys per query)

#define NTOK   512
#define FDIM   4096
#define SLICE  (256*4096)
#define PITCH  72            // smem row pitch in halfs (64 data + 8 pad)
#define PITCH4 40            // pitch for 32-k chunks (32 data + 8 pad), 16B-aligned

typedef unsigned long long u64;

// Scratch (device globals -- allocation-free per harness rules)
__device__ __align__(16) __half g_qh[2*8*256*4096];
__device__ __align__(16) __half g_kh[2*8*256*4096];
__device__ __align__(16) __half g_vh[2*8*256*4096];
__device__ __align__(16) __half g_sah[512*256*128];   // fp16 sa, [t][p][C]
__device__ __align__(16) __half g_xth[512*256*128];   // fp16 seq^T, [t][p][c]
__device__ __align__(16) __half g_wth[3*128*128];     // fp16 w_qkv [d][k]
__device__ __align__(16) __half g_wtoh[128*128];      // fp16 w_out [d][k]

// ---------------------------------------------------------------------------
// helpers
// ---------------------------------------------------------------------------
__device__ __forceinline__ void cp16h(__half* smem_dst, const __half* gsrc) {
    uint32_t s = (uint32_t)__cvta_generic_to_shared(smem_dst);
    asm volatile("cp.async.ca.shared.global [%0], [%1], 16;" :: "r"(s), "l"(gsrc));
}

__device__ __forceinline__ void ldsm4(uint32_t* r, const __half* p) {
    uint32_t a = (uint32_t)__cvta_generic_to_shared(p);
    asm volatile("ldmatrix.sync.aligned.m8n8.x4.shared.b16 {%0,%1,%2,%3}, [%4];"
                 : "=r"(r[0]), "=r"(r[1]), "=r"(r[2]), "=r"(r[3]) : "r"(a));
}

__device__ __forceinline__ void mma_f16(float* c, const uint32_t* a,
                                        uint32_t b0, uint32_t b1) {
    asm volatile(
        "mma.sync.aligned.m16n8k16.row.col.f32.f16.f16.f32 "
        "{%0,%1,%2,%3}, {%4,%5,%6,%7}, {%8,%9}, {%0,%1,%2,%3};"
        : "+f"(c[0]), "+f"(c[1]), "+f"(c[2]), "+f"(c[3])
        : "r"(a[0]), "r"(a[1]), "r"(a[2]), "r"(a[3]), "r"(b0), "r"(b1));
}

// ---- packed fp32 (B300 FFMA2 path) ----
__device__ __forceinline__ u64 pack2(float x, float y) {
    u64 r;
    asm("mov.b64 %0, {%1, %2};" : "=l"(r) : "f"(x), "f"(y));
    return r;
}
__device__ __forceinline__ void unpack2(u64 v, float& x, float& y) {
    asm("mov.b64 {%0, %1}, %2;" : "=f"(x), "=f"(y) : "l"(v));
}
__device__ __forceinline__ u64 ffma2(u64 a, u64 b, u64 c) {
    u64 d;
    asm("fma.rn.f32x2 %0, %1, %2, %3;" : "=l"(d) : "l"(a), "l"(b), "l"(c));
    return d;
}
__device__ __forceinline__ u64 h2tofx2(uint32_t h2bits) {
    float2 f = __half22float2(*reinterpret_cast<__half2*>(&h2bits));
    return pack2(f.x, f.y);
}

// ---------------------------------------------------------------------------
// prep_x: transpose seq[t][c][p] -> g_xth[t][p][c] fp16, 2 passes through a
// [128 c][129 p] float tile. First 192 blocks also convert the weights.
// (unchanged from R13 pass)
// ---------------------------------------------------------------------------
__global__ __launch_bounds__(256) void prep_x(const float* __restrict__ seq,
                                              const float* __restrict__ wq,
                                              const float* __restrict__ wo) {
    const int t = blockIdx.x;
    const int tid = threadIdx.x;
    if (t < 192) {
        int i = t * 256 + tid;   // 0..49151
        g_wth[i] = __float2half_rn(wq[i]);
        if (i < 16384) g_wtoh[i] = __float2half_rn(wo[i]);
    }

    extern __shared__ float tl[];   // [128 c][129 p_local]
    const float* src = seq + (size_t)t * 32768;
    __half* dst = g_xth + (size_t)t * 32768;

    #pragma unroll 1
    for (int pass = 0; pass < 2; pass++) {
        if (pass) __syncthreads();
        #pragma unroll
        for (int j = 0; j < 16; j++) {
            int idx = tid + j * 256;
            int c = idx >> 5, p4 = (idx & 31) * 4;
            float4 v = *reinterpret_cast<const float4*>(src + c * 256 + pass * 128 + p4);
            float* row = tl + c * 129 + p4;
            row[0] = v.x; row[1] = v.y; row[2] = v.z; row[3] = v.w;
        }
        __syncthreads();
        #pragma unroll
        for (int j = 0; j < 8; j++) {
            int idx = tid + j * 256;
            int pl = idx >> 4;
            int m = idx & 15;
            int c0 = ((m + pl) & 15) * 8;
            __half2 h[4];
            #pragma unroll
            for (int u = 0; u < 4; u++)
                h[u] = __floats2half2_rn(tl[(c0 + 2 * u) * 129 + pl],
                                         tl[(c0 + 2 * u + 1) * 129 + pl]);
            uint4 v;
            v.x = *reinterpret_cast<uint32_t*>(&h[0]);
            v.y = *reinterpret_cast<uint32_t*>(&h[1]);
            v.z = *reinterpret_cast<uint32_t*>(&h[2]);
            v.w = *reinterpret_cast<uint32_t*>(&h[3]);
            *reinterpret_cast<uint4*>(dst + (size_t)(pass * 128 + pl) * 128 + c0) = v;
        }
    }
}

// ---------------------------------------------------------------------------
// Kernel A: QKV projection, dt-merged (unchanged from R13 pass).
// ---------------------------------------------------------------------------
__global__ __launch_bounds__(256, 2) void qkv_gemm() {
    const int t  = blockIdx.x;
    const int pt = blockIdx.y;
    const int tid = threadIdx.x;
    const int lane = tid & 31, wid = tid >> 5;
    const int wm = wid >> 1, wn = wid & 1;

    extern __shared__ __align__(16) __half smem[];
    __half* Xb   = smem;                 // [2][128][72] halfs
    __half* Wbuf = smem + 18432;         // [2][128][72] halfs
    uint32_t* sst = reinterpret_cast<uint32_t*>(smem + 36864);   // 8192 words

    const __half* xmat = g_xth + (size_t)t * 32768 + pt * 16384;

    #pragma unroll
    for (int kt = 0; kt < 2; kt++)
        #pragma unroll
        for (int i = 0; i < 4; i++) {
            int id = tid + i * 256;
            int row = id >> 3, seg = (id & 7) * 8;
            cp16h(Xb + kt * 9216 + row * PITCH + seg, xmat + row * 128 + kt * 64 + seg);
        }
    asm volatile("cp.async.commit_group;" ::: "memory");

    auto issueW = [&](int dt) {
        const __half* wsrc = g_wth + dt * 16384;
        #pragma unroll
        for (int kt = 0; kt < 2; kt++) {
            #pragma unroll
            for (int i = 0; i < 4; i++) {
                int id = tid + i * 256;
                int row = id >> 3, seg = (id & 7) * 8;
                cp16h(Wbuf + kt * 9216 + row * PITCH + seg, wsrc + row * 128 + kt * 64 + seg);
            }
            asm volatile("cp.async.commit_group;" ::: "memory");
        }
    };
    issueW(0);

    const int l7 = lane & 7;
    const int aoff = (l7 + ((lane >> 3) & 1) * 8) * PITCH + ((lane >> 4) & 1) * 8;
    const int boff = (l7 + ((lane >> 4) & 1) * 8) * PITCH + ((lane >> 3) & 1) * 8;

    const int b_ = t >> 8, s_ = t & 255;

    #pragma unroll 1
    for (int dt = 0; dt < 3; dt++) {
        float acc[2][8][4];
        #pragma unroll
        for (int mf = 0; mf < 2; mf++)
            #pragma unroll
            for (int nf = 0; nf < 8; nf++)
                #pragma unroll
                for (int r = 0; r < 4; r++) acc[mf][nf][r] = 0.f;

        #pragma unroll
        for (int kt = 0; kt < 2; kt++) {
            if (kt == 0) asm volatile("cp.async.wait_group 1;" ::: "memory");
            else         asm volatile("cp.async.wait_group 0;" ::: "memory");
            __syncthreads();

            const __half* A = Wbuf + kt * 9216;
            const __half* B = Xb   + kt * 9216;

            #pragma unroll
            for (int k0 = 0; k0 < 64; k0 += 16) {
                uint32_t af[2][4], bf[4][4];
                #pragma unroll
                for (int mf = 0; mf < 2; mf++)
                    ldsm4(af[mf], A + (wm * 32 + mf * 16) * PITCH + k0 + aoff);
                #pragma unroll
                for (int np = 0; np < 4; np++)
                    ldsm4(bf[np], B + (wn * 64 + np * 16) * PITCH + k0 + boff);
                #pragma unroll
                for (int mf = 0; mf < 2; mf++)
                    #pragma unroll
                    for (int nf = 0; nf < 8; nf++)
                        mma_f16(acc[mf][nf], af[mf],
                                bf[nf >> 1][(nf & 1) * 2], bf[nf >> 1][(nf & 1) * 2 + 1]);
            }
        }
        __syncthreads();

        if (dt < 2) issueW(dt + 1);

        #pragma unroll
        for (int mf = 0; mf < 2; mf++) {
            #pragma unroll
            for (int h8 = 0; h8 < 2; h8++) {
                const int dl = wm * 32 + mf * 16 + (lane >> 2) + h8 * 8;
                const int ch = dl >> 6, cidx = dl & 63;
                #pragma unroll
                for (int nf = 0; nf < 8; nf++) {
                    const int xs = nf & 1;
                    const int hy = wn * 4 + (nf >> 1);
                    const int hidx = xs * 2 + ch;
                    __half2 hv = __floats2half2_rn(acc[mf][nf][h8 * 2],
                                                   acc[mf][nf][h8 * 2 + 1]);
                    const int word = hidx * 2048 + cidx * 32
                                   + ((hy ^ (cidx & 7)) << 2) + (lane & 3);
                    sst[word] = *reinterpret_cast<uint32_t*>(&hv);
                }
            }
        }
        __syncthreads();

        __half* dst = (dt == 0) ? g_qh : (dt == 1) ? g_kh : g_vh;
        const uint4* sst4 = reinterpret_cast<const uint4*>(sst);
        #pragma unroll
        for (int i = 0; i < 8; i++) {
            const int idx = tid + i * 256;
            const int hidx = idx >> 9, g = idx & 511;
            const int cidx = g >> 3, hy = g & 7;
            const int src = hidx * 512 + cidx * 8 + (hy ^ (cidx & 7));
            const int xs = hidx >> 1, ch = hidx & 1;
            const int n = (pt * 2 + xs) * 2 + ch;
            const size_t base = ((size_t)((b_ * 8 + n) * 256 + s_)) * FDIM + g * 8;
            *reinterpret_cast<uint4*>(dst + base) = sst4[src];
        }
    }
}

// ---------------------------------------------------------------------------
// Kernel B: masked attention, 2x2 query tiling + v-tile smem self-prefetch.
// Dynamic smem (70144 B):
//   [0, 65536)      vbuf: 8 v tiles (each thread prefetches ITS OWN 16B slice)
//   [65536, 69632)  red[16][4][16]
//   [69632, 69888)  s_sc[16][4]
//   [69888, 70144)  s_w[4][16]
//   ssa[4][64][65] aliases [0, 66560) -- used only after v phase (barrier).
// ---------------------------------------------------------------------------
__global__ __launch_bounds__(512, 2) void attn_kernel() {
    const int blk = blockIdx.x;
    const int txq = blk & 7;
    const int tyq = (blk >> 3) & 7;
    const int n   = (blk >> 6) & 7;
    const int b_  = blk >> 9;
    const int tid = threadIdx.x;
    const int lane = tid & 31, wid = tid >> 5;

    extern __shared__ float smf[];
    __half* vbuf         = (__half*)smf;                     // 32768 halfs
    float (*red)[4][16]  = (float (*)[4][16])(smf + 16384);  // 1024 floats
    float (*s_sc)[4]     = (float (*)[4])(smf + 17408);      // 64
    float (*s_w)[16]     = (float (*)[16])(smf + 17472);     // 64
    float (*ssa)[64][65] = (float (*)[64][65])smf;           // aliases vbuf

    const int qy0 = tyq * 2, qx0 = txq * 2;
    const size_t slice = (size_t)(b_ * 8 + n) * SLICE;
    const int j_safe = qy0 * 16 + qx0;

    // ---- prefetch v tiles 0..7 (own slice only) ----
    #pragma unroll
    for (int e = 0; e < 8; e++) {
        const int ky = qy0 - 1 + (e >> 2), kx = qx0 - 1 + (e & 3);
        const bool inb = (ky >= 0) & (ky < 16) & (kx >= 0) & (kx < 16);
        const int j = inb ? (ky * 16 + kx) : j_safe;
        cp16h(vbuf + e * 4096 + tid * 8, g_vh + slice + (size_t)j * FDIM + tid * 8);
    }
    asm volatile("cp.async.commit_group;" ::: "memory");

    // q for 4 queries, 8 contiguous feats/thread as 4 packed f32x2 each
    u64 qp[4][4];
    #pragma unroll
    for (int qq = 0; qq < 4; qq++) {
        const int i = (qy0 + (qq >> 1)) * 16 + qx0 + (qq & 1);
        uint4 qv = *((const uint4*)(g_qh + slice + (size_t)i * FDIM) + tid);
        qp[qq][0] = h2tofx2(qv.x); qp[qq][1] = h2tofx2(qv.y);
        qp[qq][2] = h2tofx2(qv.z); qp[qq][3] = h2tofx2(qv.w);
    }

    // ---- scores: stream 16 k tiles of the 4x4 window ----
    #pragma unroll
    for (int e = 0; e < 16; e++) {
        const int ky = qy0 - 1 + (e >> 2), kx = qx0 - 1 + (e & 3);
        const bool inb = (ky >= 0) & (ky < 16) & (kx >= 0) & (kx < 16);
        const int j = inb ? (ky * 16 + kx) : j_safe;
        uint4 kv = *((const uint4*)(g_kh + slice + (size_t)j * FDIM) + tid);
        u64 kp[4];
        kp[0] = h2tofx2(kv.x); kp[1] = h2tofx2(kv.y);
        kp[2] = h2tofx2(kv.z); kp[3] = h2tofx2(kv.w);
        float d[4];
        #pragma unroll
        for (int qq = 0; qq < 4; qq++) {
            u64 d2 = 0ull;
            #pragma unroll
            for (int u = 0; u < 4; u++) d2 = ffma2(qp[qq][u], kp[u], d2);
            float lo, hi;
            unpack2(d2, lo, hi);
            d[qq] = lo + hi;
        }
        #pragma unroll
        for (int o = 16; o > 0; o >>= 1) {
            #pragma unroll
            for (int qq = 0; qq < 4; qq++) d[qq] += __shfl_down_sync(0xffffffffu, d[qq], o);
        }
        if (lane == 0) {
            #pragma unroll
            for (int qq = 0; qq < 4; qq++) red[e][qq][wid] = d[qq];
        }
    }
    __syncthreads();

    if (tid < 64) {
        const int e = tid >> 2, qq = tid & 3;
        float s = 0.f;
        #pragma unroll
        for (int w = 0; w < 16; w++) s += red[e][qq][w];
        s_sc[e][qq] = s * 0.015625f;   // 1/sqrt(4096)
    }
    __syncthreads();

    // ---- per-query masked softmax (threads 0..3) ----
    if (tid < 4) {
        const int qq = tid;
        const int qy = qy0 + (qq >> 1), qx = qx0 + (qq & 1);
        float sc[16];
        float m = -1e30f;
        #pragma unroll
        for (int e = 0; e < 16; e++) {
            const int ky = qy0 - 1 + (e >> 2), kx = qx0 - 1 + (e & 3);
            const bool valid = (ky >= 0) & (ky < 16) & (kx >= 0) & (kx < 16)
                             & (ky >= qy - 1) & (ky <= qy + 1)
                             & (kx >= qx - 1) & (kx <= qx + 1);
            sc[e] = valid ? s_sc[e][qq] : -1e30f;
            m = fmaxf(m, sc[e]);
        }
        float sum = 0.f;
        float w[16];
        #pragma unroll
        for (int e = 0; e < 16; e++) {
            w[e] = (sc[e] > -1e29f) ? __expf(sc[e] - m) : 0.f;
            sum += w[e];
        }
        const float inv = 1.0f / sum;
        #pragma unroll
        for (int e = 0; e < 16; e++) s_w[qq][e] = w[e] * inv;
    }
    __syncthreads();

    // ---- weighted V: tiles 0..7 from smem (prefetched), 8..15 from gmem ----
    asm volatile("cp.async.wait_group 0;" ::: "memory");

    u64 fa[4][4];
    #pragma unroll
    for (int qq = 0; qq < 4; qq++)
        #pragma unroll
        for (int u = 0; u < 4; u++) fa[qq][u] = 0ull;

    #pragma unroll
    for (int e = 0; e < 16; e++) {
        const int ky = qy0 - 1 + (e >> 2), kx = qx0 - 1 + (e & 3);
        if ((ky < 0) | (ky >= 16) | (kx < 0) | (kx >= 16)) continue;
        const int j = ky * 16 + kx;
        uint4 vv;
        if (e < 8) {
            vv = *reinterpret_cast<const uint4*>(vbuf + e * 4096 + tid * 8);
        } else {
            vv = *((const uint4*)(g_vh + slice + (size_t)j * FDIM) + tid);
        }
        u64 vp[4];
        vp[0] = h2tofx2(vv.x); vp[1] = h2tofx2(vv.y);
        vp[2] = h2tofx2(vv.z); vp[3] = h2tofx2(vv.w);
        #pragma unroll
        for (int qq = 0; qq < 4; qq++) {
            const float a = s_w[qq][e];
            const u64 a2 = pack2(a, a);
            #pragma unroll
            for (int u = 0; u < 4; u++) fa[qq][u] = ffma2(a2, vp[u], fa[qq][u]);
        }
    }

    __syncthreads();   // all vbuf reads done before ssa (alias) is written

    // ---- epilogue: stage all 4 queries, then fp16 row stores ----
    const int ch = n & 1, sp = n >> 1, ys = sp >> 1, xs = sp & 1;
    const int sr0 = (tid & 7) * 8;
    const int scc = tid >> 3;
    const int r   = tid >> 3;
    const int cb  = (tid & 7) * 8;
    const int HWp = (ys * 8 + (r >> 3)) * 16 + xs * 8 + (r & 7);

    #pragma unroll
    for (int qq = 0; qq < 4; qq++) {
        #pragma unroll
        for (int u = 0; u < 4; u++) {
            float lo, hi;
            unpack2(fa[qq][u], lo, hi);
            ssa[qq][sr0 + 2 * u    ][scc] = lo;
            ssa[qq][sr0 + 2 * u + 1][scc] = hi;
        }
    }
    __syncthreads();

    #pragma unroll
    for (int qq = 0; qq < 4; qq++) {
        const int i = (qy0 + (qq >> 1)) * 16 + qx0 + (qq & 1);
        __half* rowp = g_sah + (size_t)(b_ * 256 + i) * 32768
                     + (size_t)HWp * 128 + ch * 64 + cb;
        __half2 h0 = __floats2half2_rn(ssa[qq][r][cb + 0], ssa[qq][r][cb + 1]);
        __half2 h1 = __floats2half2_rn(ssa[qq][r][cb + 2], ssa[qq][r][cb + 3]);
        __half2 h2 = __floats2half2_rn(ssa[qq][r][cb + 4], ssa[qq][r][cb + 5]);
        __half2 h3 = __floats2half2_rn(ssa[qq][r][cb + 6], ssa[qq][r][cb + 7]);
        uint4 v;
        v.x = *reinterpret_cast<uint32_t*>(&h0);
        v.y = *reinterpret_cast<uint32_t*>(&h1);
        v.z = *reinterpret_cast<uint32_t*>(&h2);
        v.w = *reinterpret_cast<uint32_t*>(&h3);
        *reinterpret_cast<uint4*>(rowp) = v;
    }
}

// ---------------------------------------------------------------------------
// Kernel C: output projection + bias. 4-stage K=32 pipeline, all stages
// issued up-front; first MMA waits on only 10KB. Pitch 40 halfs (16B-aligned
// cp.async rows; ldmatrix phases hit 8 distinct banks: 20r mod 32 distinct).
// smem: 4 stages x (A[128][40] + B[128][40]) halfs = 81920 B
// ---------------------------------------------------------------------------
__global__ __launch_bounds__(256, 2) void out_gemm(const float* __restrict__ b_out,
                                                   float* __restrict__ out) {
    const int t  = blockIdx.x;
    const int pt = blockIdx.y;
    const int tid = threadIdx.x;
    const int lane = tid & 31, wid = tid >> 5;
    const int wm = wid >> 1, wn = wid & 1;

    extern __shared__ __align__(16) __half smem[];
    const __half* xmat = g_sah + (size_t)t * 32768 + pt * 16384;

    // issue all 4 stages (one commit group each)
    #pragma unroll
    for (int st = 0; st < 4; st++) {
        __half* Ab = smem + st * 10240;
        __half* Bb = Ab + 5120;
        // 256 threads: each does 1 A-cp16 + 1 B-cp16 (128 rows x 2 segs)
        const int row = tid >> 1, seg = (tid & 1) * 8;
        cp16h(Ab + row * PITCH4 + seg, g_wtoh + row * 128 + st * 32 + seg);
        cp16h(Ab + row * PITCH4 + seg + 16, g_wtoh + row * 128 + st * 32 + seg + 16);
        cp16h(Bb + row * PITCH4 + seg, xmat + row * 128 + st * 32 + seg);
        cp16h(Bb + row * PITCH4 + seg + 16, xmat + row * 128 + st * 32 + seg + 16);
        asm volatile("cp.async.commit_group;" ::: "memory");
    }

    float acc[2][8][4];
    #pragma unroll
    for (int mf = 0; mf < 2; mf++)
        #pragma unroll
        for (int nf = 0; nf < 8; nf++)
            #pragma unroll
            for (int r = 0; r < 4; r++) acc[mf][nf][r] = 0.f;

    const int l7 = lane & 7;
    const int aoff = (l7 + ((lane >> 3) & 1) * 8) * PITCH4 + ((lane >> 4) & 1) * 8;
    const int boff = (l7 + ((lane >> 4) & 1) * 8) * PITCH4 + ((lane >> 3) & 1) * 8;

    #pragma unroll
    for (int st = 0; st < 4; st++) {
        if (st == 0)      asm volatile("cp.async.wait_group 3;" ::: "memory");
        else if (st == 1) asm volatile("cp.async.wait_group 2;" ::: "memory");
        else if (st == 2) asm volatile("cp.async.wait_group 1;" ::: "memory");
        else              asm volatile("cp.async.wait_group 0;" ::: "memory");
        __syncthreads();

        const __half* A = smem + st * 10240;
        const __half* B = A + 5120;

        #pragma unroll
        for (int k0 = 0; k0 < 32; k0 += 16) {
            uint32_t af[2][4], bf[4][4];
            #pragma unroll
            for (int mf = 0; mf < 2; mf++)
                ldsm4(af[mf], A + (wm * 32 + mf * 16) * PITCH4 + k0 + aoff);
            #pragma unroll
            for (int np = 0; np < 4; np++)
                ldsm4(bf[np], B + (wn * 64 + np * 16) * PITCH4 + k0 + boff);
            #pragma unroll
            for (int mf = 0; mf < 2; mf++)
                #pragma unroll
                for (int nf = 0; nf < 8; nf++)
                    mma_f16(acc[mf][nf], af[mf],
                            bf[nf >> 1][(nf & 1) * 2], bf[nf >> 1][(nf & 1) * 2 + 1]);
        }
    }

    #pragma unroll
    for (int mf = 0; mf < 2; mf++) {
        #pragma unroll
        for (int half_ = 0; half_ < 2; half_++) {
            const int d = wm * 32 + mf * 16 + (lane >> 2) + half_ * 8;
            const float bias = b_out[d];
            #pragma unroll
            for (int nf = 0; nf < 8; nf++) {
                const int c0 = wn * 64 + nf * 8 + 2 * (lane & 3);
                float2 v = make_float2(acc[mf][nf][half_ * 2] + bias,
                                       acc[mf][nf][half_ * 2 + 1] + bias);
                *reinterpret_cast<float2*>(out + (size_t)t * 32768
                                           + (size_t)d * 256 + pt * 128 + c0) = v;
            }
        }
    }
}

extern "C" void kernel_launch(void* const* d_in, const int* in_sizes, int n_in,
                              void* d_out, int out_size) {
    const float* seq   = (const float*)d_in[0];
    const float* w_qkv = (const float*)d_in[1];
    const float* w_out = (const float*)d_in[2];
    const float* b_out = (const float*)d_in[3];
    float* out = (float*)d_out;

    const int prepsmem = 66048;     // 128*129*4
    const int qkvsmem  = 106496;    // X 36864 + W 36864 + staging 32768
    const int outsmem  = 81920;     // 4 stages x 20480
    const int attnsmem = 70144;     // vbuf 65536 + red 4096 + s_sc 256 + s_w 256
    cudaFuncSetAttribute(prep_x,   cudaFuncAttributeMaxDynamicSharedMemorySize, prepsmem);
    cudaFuncSetAttribute(qkv_gemm, cudaFuncAttributeMaxDynamicSharedMemorySize, qkvsmem);
    cudaFuncSetAttribute(out_gemm, cudaFuncAttributeMaxDynamicSharedMemorySize, outsmem);
    cudaFuncSetAttribute(attn_kernel, cudaFuncAttributeMaxDynamicSharedMemorySize, attnsmem);

    prep_x<<<512, 256, prepsmem>>>(seq, w_qkv, w_out);

    dim3 gA(NTOK, 2);
    qkv_gemm<<<gA, 256, qkvsmem>>>();

    attn_kernel<<<1024, 512, attnsmem>>>();

    dim3 gC(NTOK, 2);
    out_gemm<<<gC, 256, outsmem>>>(b_out, out);
}

// round 15
// speedup vs baseline: 1.1452x; 1.1452x over previous
#include <cuda_runtime.h>
#include <cuda_fp16.h>
#include <cstdint>

// Problem constants (fixed by dataset):
// b=2, s=256, C=128, H=W=16, YH=XH=CH=2 -> nH=8 heads, c=64, h=w=8, D=4096
// mask: 16x16 token grid, radius-1 neighborhood (<=9 keys per query)

#define NTOK   512
#define FDIM   4096
#define SLICE  (256*4096)
#define PITCH  72            // W smem row pitch in halfs (64 data + 8 pad)
#define PITCHB 136           // X smem row pitch in halfs (128 data + 8 pad)

typedef unsigned long long u64;

// Scratch (device globals -- allocation-free per harness rules)
__device__ __align__(16) __half g_qh[2*8*256*4096];
__device__ __align__(16) __half g_kh[2*8*256*4096];
__device__ __align__(16) __half g_vh[2*8*256*4096];
__device__ __align__(16) __half g_sah[512*256*128];   // fp16 sa, [t][p][C]
__device__ __align__(16) __half g_wth[3*128*128];     // fp16 w_qkv [d][k]
__device__ __align__(16) __half g_wtoh[128*128];      // fp16 w_out [d][k]

// ---------------------------------------------------------------------------
// helpers
// ---------------------------------------------------------------------------
__device__ __forceinline__ void cp16h(__half* smem_dst, const __half* gsrc) {
    uint32_t s = (uint32_t)__cvta_generic_to_shared(smem_dst);
    asm volatile("cp.async.ca.shared.global [%0], [%1], 16;" :: "r"(s), "l"(gsrc));
}

__device__ __forceinline__ void ldsm4(uint32_t* r, const __half* p) {
    uint32_t a = (uint32_t)__cvta_generic_to_shared(p);
    asm volatile("ldmatrix.sync.aligned.m8n8.x4.shared.b16 {%0,%1,%2,%3}, [%4];"
                 : "=r"(r[0]), "=r"(r[1]), "=r"(r[2]), "=r"(r[3]) : "r"(a));
}

__device__ __forceinline__ void ldsm4t(uint32_t* r, const __half* p) {
    uint32_t a = (uint32_t)__cvta_generic_to_shared(p);
    asm volatile("ldmatrix.sync.aligned.m8n8.x4.trans.shared.b16 {%0,%1,%2,%3}, [%4];"
                 : "=r"(r[0]), "=r"(r[1]), "=r"(r[2]), "=r"(r[3]) : "r"(a));
}

__device__ __forceinline__ void mma_f16(float* c, const uint32_t* a,
                                        uint32_t b0, uint32_t b1) {
    asm volatile(
        "mma.sync.aligned.m16n8k16.row.col.f32.f16.f16.f32 "
        "{%0,%1,%2,%3}, {%4,%5,%6,%7}, {%8,%9}, {%0,%1,%2,%3};"
        : "+f"(c[0]), "+f"(c[1]), "+f"(c[2]), "+f"(c[3])
        : "r"(a[0]), "r"(a[1]), "r"(a[2]), "r"(a[3]), "r"(b0), "r"(b1));
}

// ---- packed fp32 (B300 FFMA2 path) ----
__device__ __forceinline__ u64 pack2(float x, float y) {
    u64 r;
    asm("mov.b64 %0, {%1, %2};" : "=l"(r) : "f"(x), "f"(y));
    return r;
}
__device__ __forceinline__ void unpack2(u64 v, float& x, float& y) {
    asm("mov.b64 {%0, %1}, %2;" : "=f"(x), "=f"(y) : "l"(v));
}
__device__ __forceinline__ u64 ffma2(u64 a, u64 b, u64 c) {
    u64 d;
    asm("fma.rn.f32x2 %0, %1, %2, %3;" : "=l"(d) : "l"(a), "l"(b), "l"(c));
    return d;
}
__device__ __forceinline__ u64 h2tofx2(uint32_t h2bits) {
    float2 f = __half22float2(*reinterpret_cast<__half2*>(&h2bits));
    return pack2(f.x, f.y);
}

// ---------------------------------------------------------------------------
// prep_w: weight fp32 -> fp16 (tiny; the X transpose kernel is GONE)
// ---------------------------------------------------------------------------
__global__ __launch_bounds__(256) void prep_w(const float* __restrict__ wq,
                                              const float* __restrict__ wo) {
    int i = blockIdx.x * 256 + threadIdx.x;   // grid 192 -> 49152
    g_wth[i] = __float2half_rn(wq[i]);
    if (i < 16384) g_wtoh[i] = __float2half_rn(wo[i]);
}

// ---------------------------------------------------------------------------
// Kernel A: QKV projection, dt-merged, X loaded DIRECTLY from seq (fp32) and
// converted to fp16 into a [128 c][136] smem tile (k rows, p columns). The
// B fragments come via ldmatrix.x4.trans — no global transpose needed.
// smem: X 34816 B | W [2][128][72] 36864 B | staging 32768 B = 104448 B
// ---------------------------------------------------------------------------
__global__ __launch_bounds__(256, 2) void qkv_gemm(const float* __restrict__ seq) {
    const int t  = blockIdx.x;
    const int pt = blockIdx.y;
    const int tid = threadIdx.x;
    const int lane = tid & 31, wid = tid >> 5;
    const int wm = wid >> 1, wn = wid & 1;

    extern __shared__ __align__(16) __half smem[];
    __half* Xb   = smem;                 // [128 c][PITCHB]
    __half* Wbuf = smem + 17408;         // [2][128][72]
    uint32_t* sst = reinterpret_cast<uint32_t*>(smem + 35840);   // 8192 words

    auto issueW = [&](int dt) {
        const __half* wsrc = g_wth + dt * 16384;
        #pragma unroll
        for (int kt = 0; kt < 2; kt++) {
            #pragma unroll
            for (int i = 0; i < 4; i++) {
                int id = tid + i * 256;
                int row = id >> 3, seg = (id & 7) * 8;
                cp16h(Wbuf + kt * 9216 + row * PITCH + seg, wsrc + row * 128 + kt * 64 + seg);
            }
            asm volatile("cp.async.commit_group;" ::: "memory");
        }
    };
    issueW(0);   // groups: c0, c1

    // X: LDG fp32 -> cvt -> STS (once per block; overlaps W cp.async)
    {
        const float* xsrc = seq + (size_t)t * 32768 + pt * 128;
        #pragma unroll
        for (int j = 0; j < 16; j++) {
            int idx = tid + j * 256;              // 0..4095
            int c = idx >> 5, p4 = (idx & 31) * 4;
            float4 v = *reinterpret_cast<const float4*>(xsrc + c * 256 + p4);
            __half2 h0 = __floats2half2_rn(v.x, v.y);
            __half2 h1 = __floats2half2_rn(v.z, v.w);
            uint2 u;
            u.x = *reinterpret_cast<uint32_t*>(&h0);
            u.y = *reinterpret_cast<uint32_t*>(&h1);
            *reinterpret_cast<uint2*>(Xb + c * PITCHB + p4) = u;
        }
    }

    const int l7 = lane & 7;
    const int aoff  = (l7 + ((lane >> 3) & 1) * 8) * PITCH  + ((lane >> 4) & 1) * 8;
    const int boffT = (l7 + ((lane >> 3) & 1) * 8) * PITCHB + ((lane >> 4) & 1) * 8;

    const int b_ = t >> 8, s_ = t & 255;

    #pragma unroll 1
    for (int dt = 0; dt < 3; dt++) {
        float acc[2][8][4];
        #pragma unroll
        for (int mf = 0; mf < 2; mf++)
            #pragma unroll
            for (int nf = 0; nf < 8; nf++)
                #pragma unroll
                for (int r = 0; r < 4; r++) acc[mf][nf][r] = 0.f;

        #pragma unroll
        for (int kt = 0; kt < 2; kt++) {
            if (kt == 0) asm volatile("cp.async.wait_group 1;" ::: "memory");
            else         asm volatile("cp.async.wait_group 0;" ::: "memory");
            __syncthreads();   // (dt0,kt0: also makes X STS visible)

            const __half* A = Wbuf + kt * 9216;

            #pragma unroll
            for (int k0 = 0; k0 < 64; k0 += 16) {
                const int gk = kt * 64 + k0;
                uint32_t af[2][4], bf[4][4];
                #pragma unroll
                for (int mf = 0; mf < 2; mf++)
                    ldsm4(af[mf], A + (wm * 32 + mf * 16) * PITCH + k0 + aoff);
                #pragma unroll
                for (int np = 0; np < 4; np++)
                    ldsm4t(bf[np], Xb + gk * PITCHB + wn * 64 + np * 16 + boffT);
                #pragma unroll
                for (int mf = 0; mf < 2; mf++)
                    #pragma unroll
                    for (int nf = 0; nf < 8; nf++)
                        mma_f16(acc[mf][nf], af[mf],
                                bf[nf >> 1][(nf & 1) * 2], bf[nf >> 1][(nf & 1) * 2 + 1]);
            }
        }
        __syncthreads();             // W buffer + staging fully free

        if (dt < 2) issueW(dt + 1);  // overlap next W load with epilogue

        // ---- staged epilogue (R12/R13-proven mapping) ----
        #pragma unroll
        for (int mf = 0; mf < 2; mf++) {
            #pragma unroll
            for (int h8 = 0; h8 < 2; h8++) {
                const int dl = wm * 32 + mf * 16 + (lane >> 2) + h8 * 8;
                const int ch = dl >> 6, cidx = dl & 63;
                #pragma unroll
                for (int nf = 0; nf < 8; nf++) {
                    const int xs = nf & 1;
                    const int hy = wn * 4 + (nf >> 1);
                    const int hidx = xs * 2 + ch;
                    __half2 hv = __floats2half2_rn(acc[mf][nf][h8 * 2],
                                                   acc[mf][nf][h8 * 2 + 1]);
                    const int word = hidx * 2048 + cidx * 32
                                   + ((hy ^ (cidx & 7)) << 2) + (lane & 3);
                    sst[word] = *reinterpret_cast<uint32_t*>(&hv);
                }
            }
        }
        __syncthreads();

        __half* dst = (dt == 0) ? g_qh : (dt == 1) ? g_kh : g_vh;
        const uint4* sst4 = reinterpret_cast<const uint4*>(sst);
        #pragma unroll
        for (int i = 0; i < 8; i++) {
            const int idx = tid + i * 256;               // chunk id 0..2047
            const int hidx = idx >> 9, g = idx & 511;
            const int cidx = g >> 3, hy = g & 7;
            const int src = hidx * 512 + cidx * 8 + (hy ^ (cidx & 7));
            const int xs = hidx >> 1, ch = hidx & 1;
            const int n = (pt * 2 + xs) * 2 + ch;
            const size_t base = ((size_t)((b_ * 8 + n) * 256 + s_)) * FDIM + g * 8;
            *reinterpret_cast<uint4*>(dst + base) = sst4[src];
        }
    }
}

// ---------------------------------------------------------------------------
// Kernel B: masked attention (R14-proven: 2x2 query tiling + v prefetch).
// Dynamic smem 70144 B; ssa aliases vbuf (disjoint in time, barriered).
// ---------------------------------------------------------------------------
__global__ __launch_bounds__(512, 2) void attn_kernel() {
    const int blk = blockIdx.x;
    const int txq = blk & 7;
    const int tyq = (blk >> 3) & 7;
    const int n   = (blk >> 6) & 7;
    const int b_  = blk >> 9;
    const int tid = threadIdx.x;
    const int lane = tid & 31, wid = tid >> 5;

    extern __shared__ float smf[];
    __half* vbuf         = (__half*)smf;                     // 32768 halfs
    float (*red)[4][16]  = (float (*)[4][16])(smf + 16384);  // 1024 floats
    float (*s_sc)[4]     = (float (*)[4])(smf + 17408);      // 64
    float (*s_w)[16]     = (float (*)[16])(smf + 17472);     // 64
    float (*ssa)[64][65] = (float (*)[64][65])smf;           // aliases vbuf

    const int qy0 = tyq * 2, qx0 = txq * 2;
    const size_t slice = (size_t)(b_ * 8 + n) * SLICE;
    const int j_safe = qy0 * 16 + qx0;

    // prefetch v tiles 0..7 (each thread its OWN 16B slice)
    #pragma unroll
    for (int e = 0; e < 8; e++) {
        const int ky = qy0 - 1 + (e >> 2), kx = qx0 - 1 + (e & 3);
        const bool inb = (ky >= 0) & (ky < 16) & (kx >= 0) & (kx < 16);
        const int j = inb ? (ky * 16 + kx) : j_safe;
        cp16h(vbuf + e * 4096 + tid * 8, g_vh + slice + (size_t)j * FDIM + tid * 8);
    }
    asm volatile("cp.async.commit_group;" ::: "memory");

    u64 qp[4][4];
    #pragma unroll
    for (int qq = 0; qq < 4; qq++) {
        const int i = (qy0 + (qq >> 1)) * 16 + qx0 + (qq & 1);
        uint4 qv = *((const uint4*)(g_qh + slice + (size_t)i * FDIM) + tid);
        qp[qq][0] = h2tofx2(qv.x); qp[qq][1] = h2tofx2(qv.y);
        qp[qq][2] = h2tofx2(qv.z); qp[qq][3] = h2tofx2(qv.w);
    }

    #pragma unroll
    for (int e = 0; e < 16; e++) {
        const int ky = qy0 - 1 + (e >> 2), kx = qx0 - 1 + (e & 3);
        const bool inb = (ky >= 0) & (ky < 16) & (kx >= 0) & (kx < 16);
        const int j = inb ? (ky * 16 + kx) : j_safe;
        uint4 kv = *((const uint4*)(g_kh + slice + (size_t)j * FDIM) + tid);
        u64 kp[4];
        kp[0] = h2tofx2(kv.x); kp[1] = h2tofx2(kv.y);
        kp[2] = h2tofx2(kv.z); kp[3] = h2tofx2(kv.w);
        float d[4];
        #pragma unroll
        for (int qq = 0; qq < 4; qq++) {
            u64 d2 = 0ull;
            #pragma unroll
            for (int u = 0; u < 4; u++) d2 = ffma2(qp[qq][u], kp[u], d2);
            float lo, hi;
            unpack2(d2, lo, hi);
            d[qq] = lo + hi;
        }
        #pragma unroll
        for (int o = 16; o > 0; o >>= 1) {
            #pragma unroll
            for (int qq = 0; qq < 4; qq++) d[qq] += __shfl_down_sync(0xffffffffu, d[qq], o);
        }
        if (lane == 0) {
            #pragma unroll
            for (int qq = 0; qq < 4; qq++) red[e][qq][wid] = d[qq];
        }
    }
    __syncthreads();

    if (tid < 64) {
        const int e = tid >> 2, qq = tid & 3;
        float s = 0.f;
        #pragma unroll
        for (int w = 0; w < 16; w++) s += red[e][qq][w];
        s_sc[e][qq] = s * 0.015625f;   // 1/sqrt(4096)
    }
    __syncthreads();

    if (tid < 4) {
        const int qq = tid;
        const int qy = qy0 + (qq >> 1), qx = qx0 + (qq & 1);
        float sc[16];
        float m = -1e30f;
        #pragma unroll
        for (int e = 0; e < 16; e++) {
            const int ky = qy0 - 1 + (e >> 2), kx = qx0 - 1 + (e & 3);
            const bool valid = (ky >= 0) & (ky < 16) & (kx >= 0) & (kx < 16)
                             & (ky >= qy - 1) & (ky <= qy + 1)
                             & (kx >= qx - 1) & (kx <= qx + 1);
            sc[e] = valid ? s_sc[e][qq] : -1e30f;
            m = fmaxf(m, sc[e]);
        }
        float sum = 0.f;
        float w[16];
        #pragma unroll
        for (int e = 0; e < 16; e++) {
            w[e] = (sc[e] > -1e29f) ? __expf(sc[e] - m) : 0.f;
            sum += w[e];
        }
        const float inv = 1.0f / sum;
        #pragma unroll
        for (int e = 0; e < 16; e++) s_w[qq][e] = w[e] * inv;
    }
    __syncthreads();

    asm volatile("cp.async.wait_group 0;" ::: "memory");

    u64 fa[4][4];
    #pragma unroll
    for (int qq = 0; qq < 4; qq++)
        #pragma unroll
        for (int u = 0; u < 4; u++) fa[qq][u] = 0ull;

    #pragma unroll
    for (int e = 0; e < 16; e++) {
        const int ky = qy0 - 1 + (e >> 2), kx = qx0 - 1 + (e & 3);
        if ((ky < 0) | (ky >= 16) | (kx < 0) | (kx >= 16)) continue;
        const int j = ky * 16 + kx;
        uint4 vv;
        if (e < 8) {
            vv = *reinterpret_cast<const uint4*>(vbuf + e * 4096 + tid * 8);
        } else {
            vv = *((const uint4*)(g_vh + slice + (size_t)j * FDIM) + tid);
        }
        u64 vp[4];
        vp[0] = h2tofx2(vv.x); vp[1] = h2tofx2(vv.y);
        vp[2] = h2tofx2(vv.z); vp[3] = h2tofx2(vv.w);
        #pragma unroll
        for (int qq = 0; qq < 4; qq++) {
            const float a = s_w[qq][e];
            const u64 a2 = pack2(a, a);
            #pragma unroll
            for (int u = 0; u < 4; u++) fa[qq][u] = ffma2(a2, vp[u], fa[qq][u]);
        }
    }

    __syncthreads();   // all vbuf reads done before ssa (alias) is written

    const int ch = n & 1, sp = n >> 1, ys = sp >> 1, xs = sp & 1;
    const int sr0 = (tid & 7) * 8;
    const int scc = tid >> 3;
    const int r   = tid >> 3;
    const int cb  = (tid & 7) * 8;
    const int HWp = (ys * 8 + (r >> 3)) * 16 + xs * 8 + (r & 7);

    #pragma unroll
    for (int qq = 0; qq < 4; qq++) {
        #pragma unroll
        for (int u = 0; u < 4; u++) {
            float lo, hi;
            unpack2(fa[qq][u], lo, hi);
            ssa[qq][sr0 + 2 * u    ][scc] = lo;
            ssa[qq][sr0 + 2 * u + 1][scc] = hi;
        }
    }
    __syncthreads();

    #pragma unroll
    for (int qq = 0; qq < 4; qq++) {
        const int i = (qy0 + (qq >> 1)) * 16 + qx0 + (qq & 1);
        __half* rowp = g_sah + (size_t)(b_ * 256 + i) * 32768
                     + (size_t)HWp * 128 + ch * 64 + cb;
        __half2 h0 = __floats2half2_rn(ssa[qq][r][cb + 0], ssa[qq][r][cb + 1]);
        __half2 h1 = __floats2half2_rn(ssa[qq][r][cb + 2], ssa[qq][r][cb + 3]);
        __half2 h2 = __floats2half2_rn(ssa[qq][r][cb + 4], ssa[qq][r][cb + 5]);
        __half2 h3 = __floats2half2_rn(ssa[qq][r][cb + 6], ssa[qq][r][cb + 7]);
        uint4 v;
        v.x = *reinterpret_cast<uint32_t*>(&h0);
        v.y = *reinterpret_cast<uint32_t*>(&h1);
        v.z = *reinterpret_cast<uint32_t*>(&h2);
        v.w = *reinterpret_cast<uint32_t*>(&h3);
        *reinterpret_cast<uint4*>(rowp) = v;
    }
}

// ---------------------------------------------------------------------------
// Kernel C: output projection + bias — REVERTED to R13-proven 2-stage K=64
// pipeline (pitch 72). smem: 2 x (A[128][72]+B[128][72]) = 73728 B
// ---------------------------------------------------------------------------
__global__ __launch_bounds__(256, 2) void out_gemm(const float* __restrict__ b_out,
                                                   float* __restrict__ out) {
    const int t  = blockIdx.x;
    const int pt = blockIdx.y;
    const int tid = threadIdx.x;
    const int lane = tid & 31, wid = tid >> 5;
    const int wm = wid >> 1, wn = wid & 1;

    extern __shared__ __align__(16) __half smem[];
    const __half* xmat = g_sah + (size_t)t * 32768 + pt * 16384;

    auto issue = [&](int buf, int kk) {
        __half* Ab = smem + buf * 18432;
        __half* Bb = Ab + 9216;
        #pragma unroll
        for (int i = 0; i < 4; i++) {
            int id  = tid + i * 256;
            int row = id >> 3, seg = (id & 7) * 8;
            cp16h(Ab + row * PITCH + seg, g_wtoh + row * 128 + kk + seg);
            cp16h(Bb + row * PITCH + seg, xmat + row * 128 + kk + seg);
        }
        asm volatile("cp.async.commit_group;" ::: "memory");
    };

    issue(0, 0);
    issue(1, 64);

    float acc[2][8][4];
    #pragma unroll
    for (int mf = 0; mf < 2; mf++)
        #pragma unroll
        for (int nf = 0; nf < 8; nf++)
            #pragma unroll
            for (int r = 0; r < 4; r++) acc[mf][nf][r] = 0.f;

    const int l7 = lane & 7;
    const int aoff = (l7 + ((lane >> 3) & 1) * 8) * PITCH + ((lane >> 4) & 1) * 8;
    const int boff = (l7 + ((lane >> 4) & 1) * 8) * PITCH + ((lane >> 3) & 1) * 8;

    #pragma unroll
    for (int kt = 0; kt < 2; kt++) {
        if (kt == 0) asm volatile("cp.async.wait_group 1;" ::: "memory");
        else         asm volatile("cp.async.wait_group 0;" ::: "memory");
        __syncthreads();

        const __half* A = smem + kt * 18432;
        const __half* B = A + 9216;

        #pragma unroll
        for (int k0 = 0; k0 < 64; k0 += 16) {
            uint32_t af[2][4], bf[4][4];
            #pragma unroll
            for (int mf = 0; mf < 2; mf++)
                ldsm4(af[mf], A + (wm * 32 + mf * 16) * PITCH + k0 + aoff);
            #pragma unroll
            for (int np = 0; np < 4; np++)
                ldsm4(bf[np], B + (wn * 64 + np * 16) * PITCH + k0 + boff);
            #pragma unroll
            for (int mf = 0; mf < 2; mf++)
                #pragma unroll
                for (int nf = 0; nf < 8; nf++)
                    mma_f16(acc[mf][nf], af[mf],
                            bf[nf >> 1][(nf & 1) * 2], bf[nf >> 1][(nf & 1) * 2 + 1]);
        }
    }

    #pragma unroll
    for (int mf = 0; mf < 2; mf++) {
        #pragma unroll
        for (int half_ = 0; half_ < 2; half_++) {
            const int d = wm * 32 + mf * 16 + (lane >> 2) + half_ * 8;
            const float bias = b_out[d];
            #pragma unroll
            for (int nf = 0; nf < 8; nf++) {
                const int c0 = wn * 64 + nf * 8 + 2 * (lane & 3);
                float2 v = make_float2(acc[mf][nf][half_ * 2] + bias,
                                       acc[mf][nf][half_ * 2 + 1] + bias);
                *reinterpret_cast<float2*>(out + (size_t)t * 32768
                                           + (size_t)d * 256 + pt * 128 + c0) = v;
            }
        }
    }
}

extern "C" void kernel_launch(void* const* d_in, const int* in_sizes, int n_in,
                              void* d_out, int out_size) {
    const float* seq   = (const float*)d_in[0];
    const float* w_qkv = (const float*)d_in[1];
    const float* w_out = (const float*)d_in[2];
    const float* b_out = (const float*)d_in[3];
    float* out = (float*)d_out;

    const int qkvsmem  = 104448;    // X 34816 + W 36864 + staging 32768
    const int outsmem  = 73728;
    const int attnsmem = 70144;
    cudaFuncSetAttribute(qkv_gemm, cudaFuncAttributeMaxDynamicSharedMemorySize, qkvsmem);
    cudaFuncSetAttribute(out_gemm, cudaFuncAttributeMaxDynamicSharedMemorySize, outsmem);
    cudaFuncSetAttribute(attn_kernel, cudaFuncAttributeMaxDynamicSharedMemorySize, attnsmem);

    prep_w<<<192, 256>>>(w_qkv, w_out);

    dim3 gA(NTOK, 2);
    qkv_gemm<<<gA, 256, qkvsmem>>>(seq);

    attn_kernel<<<1024, 512, attnsmem>>>();

    dim3 gC(NTOK, 2);
    out_gemm<<<gC, 256, outsmem>>>(b_out, out);
}

// round 16
// speedup vs baseline: 1.1960x; 1.0444x over previous
#include <cuda_runtime.h>
#include <cuda_fp16.h>
#include <cstdint>

// Problem constants (fixed by dataset):
// b=2, s=256, C=128, H=W=16, YH=XH=CH=2 -> nH=8 heads, c=64, h=w=8, D=4096
// mask: 16x16 token grid, radius-1 neighborhood (<=9 keys per query)

#define NTOK   512
#define FDIM   4096
#define SLICE  (256*4096)
#define PITCH  72            // W smem row pitch in halfs (64 data + 8 pad)
#define PITCHB 136           // X smem row pitch in halfs (128 data + 8 pad)

typedef unsigned long long u64;

// Scratch (device globals -- allocation-free per harness rules)
__device__ __align__(16) __half g_qh[2*8*256*4096];
__device__ __align__(16) __half g_kh[2*8*256*4096];
__device__ __align__(16) __half g_vh[2*8*256*4096];
__device__ __align__(16) __half g_sah[512*256*128];   // fp16 sa, [t][p][C]
__device__ __align__(16) __half g_wth[3*128*128];     // fp16 w_qkv [d][k]
__device__ __align__(16) __half g_wtoh[128*128];      // fp16 w_out [d][k]

// ---------------------------------------------------------------------------
// helpers
// ---------------------------------------------------------------------------
__device__ __forceinline__ void cp16h(__half* smem_dst, const __half* gsrc) {
    uint32_t s = (uint32_t)__cvta_generic_to_shared(smem_dst);
    asm volatile("cp.async.ca.shared.global [%0], [%1], 16;" :: "r"(s), "l"(gsrc));
}

__device__ __forceinline__ void ldsm4(uint32_t* r, const __half* p) {
    uint32_t a = (uint32_t)__cvta_generic_to_shared(p);
    asm volatile("ldmatrix.sync.aligned.m8n8.x4.shared.b16 {%0,%1,%2,%3}, [%4];"
                 : "=r"(r[0]), "=r"(r[1]), "=r"(r[2]), "=r"(r[3]) : "r"(a));
}

__device__ __forceinline__ void ldsm4t(uint32_t* r, const __half* p) {
    uint32_t a = (uint32_t)__cvta_generic_to_shared(p);
    asm volatile("ldmatrix.sync.aligned.m8n8.x4.trans.shared.b16 {%0,%1,%2,%3}, [%4];"
                 : "=r"(r[0]), "=r"(r[1]), "=r"(r[2]), "=r"(r[3]) : "r"(a));
}

__device__ __forceinline__ void mma_f16(float* c, const uint32_t* a,
                                        uint32_t b0, uint32_t b1) {
    asm volatile(
        "mma.sync.aligned.m16n8k16.row.col.f32.f16.f16.f32 "
        "{%0,%1,%2,%3}, {%4,%5,%6,%7}, {%8,%9}, {%0,%1,%2,%3};"
        : "+f"(c[0]), "+f"(c[1]), "+f"(c[2]), "+f"(c[3])
        : "r"(a[0]), "r"(a[1]), "r"(a[2]), "r"(a[3]), "r"(b0), "r"(b1));
}

// ---- packed fp32 (B300 FFMA2 path) ----
__device__ __forceinline__ u64 pack2(float x, float y) {
    u64 r;
    asm("mov.b64 %0, {%1, %2};" : "=l"(r) : "f"(x), "f"(y));
    return r;
}
__device__ __forceinline__ void unpack2(u64 v, float& x, float& y) {
    asm("mov.b64 {%0, %1}, %2;" : "=f"(x), "=f"(y) : "l"(v));
}
__device__ __forceinline__ u64 ffma2(u64 a, u64 b, u64 c) {
    u64 d;
    asm("fma.rn.f32x2 %0, %1, %2, %3;" : "=l"(d) : "l"(a), "l"(b), "l"(c));
    return d;
}
__device__ __forceinline__ u64 h2tofx2(uint32_t h2bits) {
    float2 f = __half22float2(*reinterpret_cast<__half2*>(&h2bits));
    return pack2(f.x, f.y);
}

// ---------------------------------------------------------------------------
// prep_w: weight fp32 -> fp16
// ---------------------------------------------------------------------------
__global__ __launch_bounds__(256) void prep_w(const float* __restrict__ wq,
                                              const float* __restrict__ wo) {
    int i = blockIdx.x * 256 + threadIdx.x;   // grid 192 -> 49152
    g_wth[i] = __float2half_rn(wq[i]);
    if (i < 16384) g_wtoh[i] = __float2half_rn(wo[i]);
}

// ---------------------------------------------------------------------------
// Kernel A: QKV projection, dt-merged, X direct from seq via trans-ldmatrix
// (unchanged from R15 pass). smem 104448 B.
// ---------------------------------------------------------------------------
__global__ __launch_bounds__(256, 2) void qkv_gemm(const float* __restrict__ seq) {
    const int t  = blockIdx.x;
    const int pt = blockIdx.y;
    const int tid = threadIdx.x;
    const int lane = tid & 31, wid = tid >> 5;
    const int wm = wid >> 1, wn = wid & 1;

    extern __shared__ __align__(16) __half smem[];
    __half* Xb   = smem;                 // [128 c][PITCHB]
    __half* Wbuf = smem + 17408;         // [2][128][72]
    uint32_t* sst = reinterpret_cast<uint32_t*>(smem + 35840);   // 8192 words

    auto issueW = [&](int dt) {
        const __half* wsrc = g_wth + dt * 16384;
        #pragma unroll
        for (int kt = 0; kt < 2; kt++) {
            #pragma unroll
            for (int i = 0; i < 4; i++) {
                int id = tid + i * 256;
                int row = id >> 3, seg = (id & 7) * 8;
                cp16h(Wbuf + kt * 9216 + row * PITCH + seg, wsrc + row * 128 + kt * 64 + seg);
            }
            asm volatile("cp.async.commit_group;" ::: "memory");
        }
    };
    issueW(0);

    {
        const float* xsrc = seq + (size_t)t * 32768 + pt * 128;
        #pragma unroll
        for (int j = 0; j < 16; j++) {
            int idx = tid + j * 256;
            int c = idx >> 5, p4 = (idx & 31) * 4;
            float4 v = *reinterpret_cast<const float4*>(xsrc + c * 256 + p4);
            __half2 h0 = __floats2half2_rn(v.x, v.y);
            __half2 h1 = __floats2half2_rn(v.z, v.w);
            uint2 u;
            u.x = *reinterpret_cast<uint32_t*>(&h0);
            u.y = *reinterpret_cast<uint32_t*>(&h1);
            *reinterpret_cast<uint2*>(Xb + c * PITCHB + p4) = u;
        }
    }

    const int l7 = lane & 7;
    const int aoff  = (l7 + ((lane >> 3) & 1) * 8) * PITCH  + ((lane >> 4) & 1) * 8;
    const int boffT = (l7 + ((lane >> 3) & 1) * 8) * PITCHB + ((lane >> 4) & 1) * 8;

    const int b_ = t >> 8, s_ = t & 255;

    #pragma unroll 1
    for (int dt = 0; dt < 3; dt++) {
        float acc[2][8][4];
        #pragma unroll
        for (int mf = 0; mf < 2; mf++)
            #pragma unroll
            for (int nf = 0; nf < 8; nf++)
                #pragma unroll
                for (int r = 0; r < 4; r++) acc[mf][nf][r] = 0.f;

        #pragma unroll
        for (int kt = 0; kt < 2; kt++) {
            if (kt == 0) asm volatile("cp.async.wait_group 1;" ::: "memory");
            else         asm volatile("cp.async.wait_group 0;" ::: "memory");
            __syncthreads();

            const __half* A = Wbuf + kt * 9216;

            #pragma unroll
            for (int k0 = 0; k0 < 64; k0 += 16) {
                const int gk = kt * 64 + k0;
                uint32_t af[2][4], bf[4][4];
                #pragma unroll
                for (int mf = 0; mf < 2; mf++)
                    ldsm4(af[mf], A + (wm * 32 + mf * 16) * PITCH + k0 + aoff);
                #pragma unroll
                for (int np = 0; np < 4; np++)
                    ldsm4t(bf[np], Xb + gk * PITCHB + wn * 64 + np * 16 + boffT);
                #pragma unroll
                for (int mf = 0; mf < 2; mf++)
                    #pragma unroll
                    for (int nf = 0; nf < 8; nf++)
                        mma_f16(acc[mf][nf], af[mf],
                                bf[nf >> 1][(nf & 1) * 2], bf[nf >> 1][(nf & 1) * 2 + 1]);
            }
        }
        __syncthreads();

        if (dt < 2) issueW(dt + 1);

        #pragma unroll
        for (int mf = 0; mf < 2; mf++) {
            #pragma unroll
            for (int h8 = 0; h8 < 2; h8++) {
                const int dl = wm * 32 + mf * 16 + (lane >> 2) + h8 * 8;
                const int ch = dl >> 6, cidx = dl & 63;
                #pragma unroll
                for (int nf = 0; nf < 8; nf++) {
                    const int xs = nf & 1;
                    const int hy = wn * 4 + (nf >> 1);
                    const int hidx = xs * 2 + ch;
                    __half2 hv = __floats2half2_rn(acc[mf][nf][h8 * 2],
                                                   acc[mf][nf][h8 * 2 + 1]);
                    const int word = hidx * 2048 + cidx * 32
                                   + ((hy ^ (cidx & 7)) << 2) + (lane & 3);
                    sst[word] = *reinterpret_cast<uint32_t*>(&hv);
                }
            }
        }
        __syncthreads();

        __half* dst = (dt == 0) ? g_qh : (dt == 1) ? g_kh : g_vh;
        const uint4* sst4 = reinterpret_cast<const uint4*>(sst);
        #pragma unroll
        for (int i = 0; i < 8; i++) {
            const int idx = tid + i * 256;
            const int hidx = idx >> 9, g = idx & 511;
            const int cidx = g >> 3, hy = g & 7;
            const int src = hidx * 512 + cidx * 8 + (hy ^ (cidx & 7));
            const int xs = hidx >> 1, ch = hidx & 1;
            const int n = (pt * 2 + xs) * 2 + ch;
            const size_t base = ((size_t)((b_ * 8 + n) * 256 + s_)) * FDIM + g * 8;
            *reinterpret_cast<uint4*>(dst + base) = sst4[src];
        }
    }
}

// ---------------------------------------------------------------------------
// Kernel B: masked attention. Changes vs R15:
//  - score dots in native __hfma2 (no k conversions; q kept as fp16 regs)
//  - shuffle tree 5 -> 3 levels; lanes<4 write 64 partials/tile to red2
//    ([16][4][65] pitch-65 floats, <=2-way conflict final sum)
// Dynamic smem (82816 B):
//   [0, 65536)      vbuf (8 v tiles)       | ssa[4][64][65] aliases [0,66560)
//   [65536, 82176)  red2[16][4][65]
//   [82176, 82432)  s_sc[16][4]
//   [82432, 82688)  s_w[4][16]
// ---------------------------------------------------------------------------
__global__ __launch_bounds__(512, 2) void attn_kernel() {
    const int blk = blockIdx.x;
    const int txq = blk & 7;
    const int tyq = (blk >> 3) & 7;
    const int n   = (blk >> 6) & 7;
    const int b_  = blk >> 9;
    const int tid = threadIdx.x;
    const int lane = tid & 31, wid = tid >> 5;

    extern __shared__ float smf[];
    __half* vbuf          = (__half*)smf;                     // 32768 halfs
    float (*red2)[4][65]  = (float (*)[4][65])(smf + 16384);  // 4160 floats
    float (*s_sc)[4]      = (float (*)[4])(smf + 20544);      // 64
    float (*s_w)[16]      = (float (*)[16])(smf + 20608);     // 64
    float (*ssa)[64][65]  = (float (*)[64][65])smf;           // aliases vbuf

    const int qy0 = tyq * 2, qx0 = txq * 2;
    const size_t slice = (size_t)(b_ * 8 + n) * SLICE;
    const int j_safe = qy0 * 16 + qx0;

    // prefetch v tiles 0..7 (each thread its OWN 16B slice)
    #pragma unroll
    for (int e = 0; e < 8; e++) {
        const int ky = qy0 - 1 + (e >> 2), kx = qx0 - 1 + (e & 3);
        const bool inb = (ky >= 0) & (ky < 16) & (kx >= 0) & (kx < 16);
        const int j = inb ? (ky * 16 + kx) : j_safe;
        cp16h(vbuf + e * 4096 + tid * 8, g_vh + slice + (size_t)j * FDIM + tid * 8);
    }
    asm volatile("cp.async.commit_group;" ::: "memory");

    // q for 4 queries: keep native fp16 (4 x uint4 = 16 regs)
    uint4 qv[4];
    #pragma unroll
    for (int qq = 0; qq < 4; qq++) {
        const int i = (qy0 + (qq >> 1)) * 16 + qx0 + (qq & 1);
        qv[qq] = *((const uint4*)(g_qh + slice + (size_t)i * FDIM) + tid);
    }

    // ---- scores: 16 k tiles, hfma2 dots, 3-level shuffle + smem stage ----
    #pragma unroll
    for (int e = 0; e < 16; e++) {
        const int ky = qy0 - 1 + (e >> 2), kx = qx0 - 1 + (e & 3);
        const bool inb = (ky >= 0) & (ky < 16) & (kx >= 0) & (kx < 16);
        const int j = inb ? (ky * 16 + kx) : j_safe;
        uint4 kv = *((const uint4*)(g_kh + slice + (size_t)j * FDIM) + tid);
        const __half2* kh = reinterpret_cast<const __half2*>(&kv);
        float d[4];
        #pragma unroll
        for (int qq = 0; qq < 4; qq++) {
            const __half2* q2 = reinterpret_cast<const __half2*>(&qv[qq]);
            __half2 acc = __hmul2(q2[0], kh[0]);
            acc = __hfma2(q2[1], kh[1], acc);
            acc = __hfma2(q2[2], kh[2], acc);
            acc = __hfma2(q2[3], kh[3], acc);
            float2 f = __half22float2(acc);
            d[qq] = f.x + f.y;
        }
        #pragma unroll
        for (int o = 16; o >= 4; o >>= 1) {
            #pragma unroll
            for (int qq = 0; qq < 4; qq++) d[qq] += __shfl_down_sync(0xffffffffu, d[qq], o);
        }
        if (lane < 4) {
            #pragma unroll
            for (int qq = 0; qq < 4; qq++) red2[e][qq][wid * 4 + lane] = d[qq];
        }
    }
    __syncthreads();

    if (tid < 64) {
        const int e = tid >> 2, qq = tid & 3;
        float s = 0.f;
        #pragma unroll
        for (int w = 0; w < 64; w++) s += red2[e][qq][w];
        s_sc[e][qq] = s * 0.015625f;   // 1/sqrt(4096)
    }
    __syncthreads();

    // ---- per-query masked softmax (threads 0..3) ----
    if (tid < 4) {
        const int qq = tid;
        const int qy = qy0 + (qq >> 1), qx = qx0 + (qq & 1);
        float sc[16];
        float m = -1e30f;
        #pragma unroll
        for (int e = 0; e < 16; e++) {
            const int ky = qy0 - 1 + (e >> 2), kx = qx0 - 1 + (e & 3);
            const bool valid = (ky >= 0) & (ky < 16) & (kx >= 0) & (kx < 16)
                             & (ky >= qy - 1) & (ky <= qy + 1)
                             & (kx >= qx - 1) & (kx <= qx + 1);
            sc[e] = valid ? s_sc[e][qq] : -1e30f;
            m = fmaxf(m, sc[e]);
        }
        float sum = 0.f;
        float w[16];
        #pragma unroll
        for (int e = 0; e < 16; e++) {
            w[e] = (sc[e] > -1e29f) ? __expf(sc[e] - m) : 0.f;
            sum += w[e];
        }
        const float inv = 1.0f / sum;
        #pragma unroll
        for (int e = 0; e < 16; e++) s_w[qq][e] = w[e] * inv;
    }
    __syncthreads();

    // ---- weighted V (fp32 f32x2 accumulate, unchanged precision) ----
    asm volatile("cp.async.wait_group 0;" ::: "memory");

    u64 fa[4][4];
    #pragma unroll
    for (int qq = 0; qq < 4; qq++)
        #pragma unroll
        for (int u = 0; u < 4; u++) fa[qq][u] = 0ull;

    #pragma unroll
    for (int e = 0; e < 16; e++) {
        const int ky = qy0 - 1 + (e >> 2), kx = qx0 - 1 + (e & 3);
        if ((ky < 0) | (ky >= 16) | (kx < 0) | (kx >= 16)) continue;
        const int j = ky * 16 + kx;
        uint4 vv;
        if (e < 8) {
            vv = *reinterpret_cast<const uint4*>(vbuf + e * 4096 + tid * 8);
        } else {
            vv = *((const uint4*)(g_vh + slice + (size_t)j * FDIM) + tid);
        }
        u64 vp[4];
        vp[0] = h2tofx2(vv.x); vp[1] = h2tofx2(vv.y);
        vp[2] = h2tofx2(vv.z); vp[3] = h2tofx2(vv.w);
        #pragma unroll
        for (int qq = 0; qq < 4; qq++) {
            const float a = s_w[qq][e];
            const u64 a2 = pack2(a, a);
            #pragma unroll
            for (int u = 0; u < 4; u++) fa[qq][u] = ffma2(a2, vp[u], fa[qq][u]);
        }
    }

    __syncthreads();   // all vbuf reads done before ssa (alias) is written

    // ---- epilogue: stage all 4 queries, then fp16 row stores ----
    const int ch = n & 1, sp = n >> 1, ys = sp >> 1, xs = sp & 1;
    const int sr0 = (tid & 7) * 8;
    const int scc = tid >> 3;
    const int r   = tid >> 3;
    const int cb  = (tid & 7) * 8;
    const int HWp = (ys * 8 + (r >> 3)) * 16 + xs * 8 + (r & 7);

    #pragma unroll
    for (int qq = 0; qq < 4; qq++) {
        #pragma unroll
        for (int u = 0; u < 4; u++) {
            float lo, hi;
            unpack2(fa[qq][u], lo, hi);
            ssa[qq][sr0 + 2 * u    ][scc] = lo;
            ssa[qq][sr0 + 2 * u + 1][scc] = hi;
        }
    }
    __syncthreads();

    #pragma unroll
    for (int qq = 0; qq < 4; qq++) {
        const int i = (qy0 + (qq >> 1)) * 16 + qx0 + (qq & 1);
        __half* rowp = g_sah + (size_t)(b_ * 256 + i) * 32768
                     + (size_t)HWp * 128 + ch * 64 + cb;
        __half2 h0 = __floats2half2_rn(ssa[qq][r][cb + 0], ssa[qq][r][cb + 1]);
        __half2 h1 = __floats2half2_rn(ssa[qq][r][cb + 2], ssa[qq][r][cb + 3]);
        __half2 h2 = __floats2half2_rn(ssa[qq][r][cb + 4], ssa[qq][r][cb + 5]);
        __half2 h3 = __floats2half2_rn(ssa[qq][r][cb + 6], ssa[qq][r][cb + 7]);
        uint4 v;
        v.x = *reinterpret_cast<uint32_t*>(&h0);
        v.y = *reinterpret_cast<uint32_t*>(&h1);
        v.z = *reinterpret_cast<uint32_t*>(&h2);
        v.w = *reinterpret_cast<uint32_t*>(&h3);
        *reinterpret_cast<uint4*>(rowp) = v;
    }
}

// ---------------------------------------------------------------------------
// Kernel C: output projection + bias (R13/R15-proven 2-stage pipeline)
// ---------------------------------------------------------------------------
__global__ __launch_bounds__(256, 2) void out_gemm(const float* __restrict__ b_out,
                                                   float* __restrict__ out) {
    const int t  = blockIdx.x;
    const int pt = blockIdx.y;
    const int tid = threadIdx.x;
    const int lane = tid & 31, wid = tid >> 5;
    const int wm = wid >> 1, wn = wid & 1;

    extern __shared__ __align__(16) __half smem[];
    const __half* xmat = g_sah + (size_t)t * 32768 + pt * 16384;

    auto issue = [&](int buf, int kk) {
        __half* Ab = smem + buf * 18432;
        __half* Bb = Ab + 9216;
        #pragma unroll
        for (int i = 0; i < 4; i++) {
            int id  = tid + i * 256;
            int row = id >> 3, seg = (id & 7) * 8;
            cp16h(Ab + row * PITCH + seg, g_wtoh + row * 128 + kk + seg);
            cp16h(Bb + row * PITCH + seg, xmat + row * 128 + kk + seg);
        }
        asm volatile("cp.async.commit_group;" ::: "memory");
    };

    issue(0, 0);
    issue(1, 64);

    float acc[2][8][4];
    #pragma unroll
    for (int mf = 0; mf < 2; mf++)
        #pragma unroll
        for (int nf = 0; nf < 8; nf++)
            #pragma unroll
            for (int r = 0; r < 4; r++) acc[mf][nf][r] = 0.f;

    const int l7 = lane & 7;
    const int aoff = (l7 + ((lane >> 3) & 1) * 8) * PITCH + ((lane >> 4) & 1) * 8;
    const int boff = (l7 + ((lane >> 4) & 1) * 8) * PITCH + ((lane >> 3) & 1) * 8;

    #pragma unroll
    for (int kt = 0; kt < 2; kt++) {
        if (kt == 0) asm volatile("cp.async.wait_group 1;" ::: "memory");
        else         asm volatile("cp.async.wait_group 0;" ::: "memory");
        __syncthreads();

        const __half* A = smem + kt * 18432;
        const __half* B = A + 9216;

        #pragma unroll
        for (int k0 = 0; k0 < 64; k0 += 16) {
            uint32_t af[2][4], bf[4][4];
            #pragma unroll
            for (int mf = 0; mf < 2; mf++)
                ldsm4(af[mf], A + (wm * 32 + mf * 16) * PITCH + k0 + aoff);
            #pragma unroll
            for (int np = 0; np < 4; np++)
                ldsm4(bf[np], B + (wn * 64 + np * 16) * PITCH + k0 + boff);
            #pragma unroll
            for (int mf = 0; mf < 2; mf++)
                #pragma unroll
                for (int nf = 0; nf < 8; nf++)
                    mma_f16(acc[mf][nf], af[mf],
                            bf[nf >> 1][(nf & 1) * 2], bf[nf >> 1][(nf & 1) * 2 + 1]);
        }
    }

    #pragma unroll
    for (int mf = 0; mf < 2; mf++) {
        #pragma unroll
        for (int half_ = 0; half_ < 2; half_++) {
            const int d = wm * 32 + mf * 16 + (lane >> 2) + half_ * 8;
            const float bias = b_out[d];
            #pragma unroll
            for (int nf = 0; nf < 8; nf++) {
                const int c0 = wn * 64 + nf * 8 + 2 * (lane & 3);
                float2 v = make_float2(acc[mf][nf][half_ * 2] + bias,
                                       acc[mf][nf][half_ * 2 + 1] + bias);
                *reinterpret_cast<float2*>(out + (size_t)t * 32768
                                           + (size_t)d * 256 + pt * 128 + c0) = v;
            }
        }
    }
}

extern "C" void kernel_launch(void* const* d_in, const int* in_sizes, int n_in,
                              void* d_out, int out_size) {
    const float* seq   = (const float*)d_in[0];
    const float* w_qkv = (const float*)d_in[1];
    const float* w_out = (const float*)d_in[2];
    const float* b_out = (const float*)d_in[3];
    float* out = (float*)d_out;

    const int qkvsmem  = 104448;    // X 34816 + W 36864 + staging 32768
    const int outsmem  = 73728;
    const int attnsmem = 82688;     // vbuf 65536 + red2 16640 + s_sc 256 + s_w 256
    cudaFuncSetAttribute(qkv_gemm, cudaFuncAttributeMaxDynamicSharedMemorySize, qkvsmem);
    cudaFuncSetAttribute(out_gemm, cudaFuncAttributeMaxDynamicSharedMemorySize, outsmem);
    cudaFuncSetAttribute(attn_kernel, cudaFuncAttributeMaxDynamicSharedMemorySize, attnsmem);

    prep_w<<<192, 256>>>(w_qkv, w_out);

    dim3 gA(NTOK, 2);
    qkv_gemm<<<gA, 256, qkvsmem>>>(seq);

    attn_kernel<<<1024, 512, attnsmem>>>();

    dim3 gC(NTOK, 2);
    out_gemm<<<gC, 256, outsmem>>>(b_out, out);
}